// round 3
// baseline (speedup 1.0000x reference)
#include <cuda_runtime.h>
#include <cstdint>

#define CTC_V  128
#define NEG2   (-1.0e30f)
#define DSLOT  128          // boundary ring depth per warp (power of 2)
#define MAXW   17           // warps for S=513
#define MAXBD  (MAXW * 32)  // 544

// Scratch: log2-softmax probabilities (T*B*V) and per-example costs (nats).
__device__ float g_probs[1024 * 64 * 128];
__device__ float g_costs[1024];

// ---------------------------------------------------------------------------
// fast MUFU intrinsics (guaranteed EX2/LG2)
// ---------------------------------------------------------------------------
__device__ __forceinline__ float ex2(float x) {
    float y; asm("ex2.approx.ftz.f32 %0, %1;" : "=f"(y) : "f"(x)); return y;
}
__device__ __forceinline__ float lg2(float x) {
    float y; asm("lg2.approx.ftz.f32 %0, %1;" : "=f"(y) : "f"(x)); return y;
}

// ---------------------------------------------------------------------------
// Kernel 1: log2-softmax over V=128 per (t,b) row. One warp per row, float4 IO.
// ---------------------------------------------------------------------------
__global__ void softmax_k(const float* __restrict__ acts, int rows) {
    int gw   = (blockIdx.x * blockDim.x + threadIdx.x) >> 5;
    int lane = threadIdx.x & 31;
    if (gw >= rows) return;
    const float L2E = 1.4426950408889634f;
    const float4* src = reinterpret_cast<const float4*>(acts) + (size_t)gw * 32 + lane;
    float4 v = *src;
    float x0 = v.x * L2E, x1 = v.y * L2E, x2 = v.z * L2E, x3 = v.w * L2E;
    float m = fmaxf(fmaxf(x0, x1), fmaxf(x2, x3));
#pragma unroll
    for (int o = 16; o; o >>= 1) m = fmaxf(m, __shfl_xor_sync(0xffffffffu, m, o));
    float ssum = ex2(x0 - m) + ex2(x1 - m) + ex2(x2 - m) + ex2(x3 - m);
#pragma unroll
    for (int o = 16; o; o >>= 1) ssum += __shfl_xor_sync(0xffffffffu, ssum, o);
    float ls = lg2(ssum) + m;
    float4 o4 = make_float4(x0 - ls, x1 - ls, x2 - ls, x3 - ls);
    reinterpret_cast<float4*>(g_probs)[(size_t)gw * 32 + lane] = o4;
}

// ---------------------------------------------------------------------------
// boundary slot helpers: 16B slot = {b30, b31, tag, pad}; release/acquire tag.
// ---------------------------------------------------------------------------
__device__ __forceinline__ void slot_pub(uint32_t addr, float b30, float b31, unsigned tag) {
    asm volatile("st.shared.v2.f32 [%0], {%1, %2};" :: "r"(addr), "f"(b30), "f"(b31));
    asm volatile("st.release.cta.shared.b32 [%0], %1;" :: "r"(addr + 8), "r"(tag) : "memory");
}
__device__ __forceinline__ void slot_wait(uint32_t addr, unsigned want, float& b30, float& b31) {
    unsigned tg;
    do {
        asm volatile("ld.acquire.cta.shared.b32 %0, [%1];" : "=r"(tg) : "r"(addr + 8) : "memory");
    } while (tg != want);
    asm volatile("ld.shared.v2.f32 {%0, %1}, [%2];" : "=f"(b30), "=f"(b31) : "r"(addr));
}

// ---------------------------------------------------------------------------
// Kernel 2: CTC alpha recursion, log2 domain, skewed per-warp wavefront.
// One CTA per batch element; each warp owns 32 contiguous extended states in
// registers; s-1/s-2 via shfl_up; warp boundaries via tagged ring slots; NO
// __syncthreads in the time loop.
// ---------------------------------------------------------------------------
__global__ __launch_bounds__(MAXBD, 1) void ctc_alpha_k(
    const int* __restrict__ labels, const int* __restrict__ act_lens,
    const int* __restrict__ label_lens, int T, int B, int L)
{
    __shared__ float4   slots[MAXW][DSLOT];
    __shared__ unsigned prog[MAXW];
    __shared__ float    sh_alpha[MAXBD];

    const int V = CTC_V;
    int b    = blockIdx.x;
    int S    = 2 * L + 1;
    int tid  = threadIdx.x;
    int lane = tid & 31, w = tid >> 5;
    int NW   = blockDim.x >> 5;

    int Tlen = act_lens[b];
    if (Tlen > T) Tlen = T;
    if (Tlen < 1) Tlen = 1;
    int Lb = label_lens[b];

    // init ring tags (invalid) and progress counters
    for (int i = tid; i < MAXW * DSLOT; i += blockDim.x)
        (&slots[0][0])[i] = make_float4(0.f, 0.f, __uint_as_float(0xFFFFFFFFu), 0.f);
    if (tid < MAXW) prog[tid] = 0;

    // per-thread extended-label value and skip mask
    int  s      = tid;
    int  extv   = 0;
    bool allow  = false;
    bool active = (s < S);
    if ((s & 1) && s < S) {
        extv = labels[b * L + (s >> 1)];
        if (s >= 3) allow = (extv != labels[b * L + ((s - 2) >> 1)]);
    }

    const float* pbase   = g_probs + (size_t)b * V + extv;   // per-thread emit base
    const size_t rstride = (size_t)B * V;

    __syncthreads();   // ring/prog init visible to all warps

    // t = 0 init
    float c = (s < 2) ? __ldg(pbase) : NEG2;

    // shared addresses
    uint32_t sbase = (uint32_t)__cvta_generic_to_shared(&slots[0][0]);
    uint32_t my    = sbase + (uint32_t)w * DSLOT * 16u;
    uint32_t lf    = sbase + (uint32_t)(w - 1) * DSLOT * 16u;
    volatile unsigned* vprog = prog;

    // emit prefetch pipeline (depth 4)
    float em[4];
#pragma unroll
    for (int j = 0; j < 4; ++j) {
        int tt = 1 + j;
        em[j] = (tt < Tlen) ? __ldg(pbase + (size_t)tt * rstride) : 0.0f;
    }

    const bool is_prod = (w < NW - 1);
    const bool is_cons = (w > 0);

#pragma unroll 4
    for (int t = 1; t < Tlen; ++t) {
        float p1 = __shfl_up_sync(0xffffffffu, c, 1);
        float p2 = __shfl_up_sync(0xffffffffu, c, 2);

        uint32_t so = (uint32_t)((t - 1) & (DSLOT - 1)) * 16u;
        if (is_prod && lane == 31) slot_pub(my + so, p1, c, (unsigned)(t - 1));

        if (is_cons) {
            float b30, b31;
            slot_wait(lf + so, (unsigned)(t - 1), b30, b31);
            if (lane == 0) { p1 = b31; p2 = b30; }
            else if (lane == 1) { p2 = b31; }
        } else {
            if (lane == 0) { p1 = NEG2; p2 = NEG2; }
            else if (lane == 1) { p2 = NEG2; }
        }

        float p2m = allow ? p2 : NEG2;
        float m   = fmaxf(fmaxf(c, p1), p2m);
        float r   = ex2(c - m) + ex2(p1 - m) + ex2(p2m - m);
        float nv  = m + lg2(r) + em[(t - 1) & 3];
        c = active ? nv : NEG2;

        int tn = t + 4;
        if (tn < Tlen) em[(t - 1) & 3] = __ldg(pbase + (size_t)tn * rstride);

        // progress + backpressure (every 32 steps)
        if ((t & 31) == 0) {
            if (is_cons && lane == 0) vprog[w] = (unsigned)t;
            if (is_prod) {
                while ((int)((unsigned)t - vprog[w + 1]) > 48) { }
            }
        }
    }

    sh_alpha[tid] = c;
    __syncthreads();

    if (tid == 0) {
        int end = 2 * Lb;
        if (end > S - 1) end = S - 1;
        float a0 = sh_alpha[end];
        float a1 = (end >= 1) ? sh_alpha[end - 1] : NEG2;
        float mm = fmaxf(a0, a1);
        float l2sum = mm + lg2(ex2(a0 - mm) + ex2(a1 - mm));
        g_costs[b] = -l2sum * 0.69314718055994530942f;   // log2 -> nats
    }
}

// ---------------------------------------------------------------------------
// Kernel 3: deterministic sum of per-example costs.
// ---------------------------------------------------------------------------
__global__ void reduce_k(float* out, int B) {
    float sum = 0.0f;
    for (int i = threadIdx.x; i < B; i += 32) sum += g_costs[i];
#pragma unroll
    for (int o = 16; o; o >>= 1) sum += __shfl_xor_sync(0xffffffffu, sum, o);
    if (threadIdx.x == 0) *out = sum;
}

// ---------------------------------------------------------------------------
extern "C" void kernel_launch(void* const* d_in, const int* in_sizes, int n_in,
                              void* d_out, int out_size)
{
    const float* acts      = (const float*)d_in[0];
    const int*   labels    = (const int*)d_in[1];
    const int*   act_lens  = (const int*)d_in[2];
    const int*   label_len = (const int*)d_in[3];

    int B = in_sizes[2];
    int L = in_sizes[1] / B;
    int V = CTC_V;
    int T = in_sizes[0] / (B * V);

    int rows = T * B;
    softmax_k<<<(rows + 7) / 8, 256>>>(acts, rows);

    int S  = 2 * L + 1;
    int BD = ((S + 31) / 32) * 32;   // 544 for L=256
    ctc_alpha_k<<<B, BD>>>(labels, act_lens, label_len, T, B, L);

    reduce_k<<<1, 32>>>((float*)d_out, B);
}

// round 5
// speedup vs baseline: 3.4735x; 3.4735x over previous
#include <cuda_runtime.h>
#include <cstdint>

#define CTC_V  128
#define NEG2   (-1.0e30f)
#define KSTEP  4                 // time steps per barrier
#define UW     (32 - KSTEP)      // useful lanes per warp

// Scratch: log2-softmax probs (T*B*V), compact blank probs (B*T), costs.
__device__ float g_probs[1024 * 64 * 128];
__device__ float g_blank[64 * 1024];
__device__ float g_costs[1024];

__device__ __forceinline__ float ex2(float x) {
    float y; asm("ex2.approx.ftz.f32 %0, %1;" : "=f"(y) : "f"(x)); return y;
}
__device__ __forceinline__ float lg2(float x) {
    float y; asm("lg2.approx.ftz.f32 %0, %1;" : "=f"(y) : "f"(x)); return y;
}

// ---------------------------------------------------------------------------
// Kernel 1: log2-softmax over V=128 per (t,b) row. One warp per row.
// Also writes the blank (v=0) log2-prob to the compact [B][T] array.
// ---------------------------------------------------------------------------
__global__ void softmax_k(const float* __restrict__ acts, int rows, int T, int B) {
    int gw   = (blockIdx.x * blockDim.x + threadIdx.x) >> 5;
    int lane = threadIdx.x & 31;
    if (gw >= rows) return;
    const float L2E = 1.4426950408889634f;
    const float4* src = reinterpret_cast<const float4*>(acts) + (size_t)gw * 32 + lane;
    float4 v = *src;
    float x0 = v.x * L2E, x1 = v.y * L2E, x2 = v.z * L2E, x3 = v.w * L2E;
    float m = fmaxf(fmaxf(x0, x1), fmaxf(x2, x3));
#pragma unroll
    for (int o = 16; o; o >>= 1) m = fmaxf(m, __shfl_xor_sync(0xffffffffu, m, o));
    float ssum = ex2(x0 - m) + ex2(x1 - m) + ex2(x2 - m) + ex2(x3 - m);
#pragma unroll
    for (int o = 16; o; o >>= 1) ssum += __shfl_xor_sync(0xffffffffu, ssum, o);
    float ls = lg2(ssum) + m;
    float4 o4 = make_float4(x0 - ls, x1 - ls, x2 - ls, x3 - ls);
    reinterpret_cast<float4*>(g_probs)[(size_t)gw * 32 + lane] = o4;
    if (lane == 0) {
        int t = gw / B, b = gw - t * B;
        g_blank[b * T + t] = x0 - ls;   // v = 0 element
    }
}

// ---------------------------------------------------------------------------
// Kernel 2: CTC alpha recursion, log2 domain, pair-per-thread, K steps per
// barrier with K halo lanes per warp. One CTA per batch element.
//   pair p owns states s0=2p (blank) and s1=2p+1 (label p).
//   step: s0' = logadd(c0, c1[p-1]) + eb
//         s1' = logadd(c1, c0, allow? c1[p-1]) + el
// ---------------------------------------------------------------------------
extern __shared__ float2 sh_pairs[];   // 2 buffers of (P+1) float2

__global__ __launch_bounds__(320, 1) void ctc_alpha_k(
    const int* __restrict__ labels, const int* __restrict__ act_lens,
    const int* __restrict__ label_lens, int T, int B, int L)
{
    const int V = CTC_V;
    const int b = blockIdx.x;
    const int P = L + 1;                       // number of pairs
    const int tid = threadIdx.x;
    const int lane = tid & 31, w = tid >> 5;

    float2* sh0 = sh_pairs;
    float2* sh1 = sh_pairs + (P + 1);

    int Tlen = act_lens[b];
    if (Tlen > T) Tlen = T;
    if (Tlen < 1) Tlen = 1;
    const int Lb = label_lens[b];

    const int p = w * UW + lane - KSTEP;       // pair index (may be <0 / >=P)
    const bool inP  = ((unsigned)p < (unsigned)P);
    const bool act0 = inP;                     // blank state 2p exists
    const bool act1 = ((unsigned)p < (unsigned)L);
    int  extv  = act1 ? labels[b * L + p] : 0;
    bool allow = act1 && (p >= 1) && (extv != labels[b * L + p - 1]);
    const bool useful = (lane >= KSTEP) && inP;

    const float* __restrict__ pl = g_probs + (size_t)b * V + extv;  // label stream
    const float* __restrict__ pb = g_blank + (size_t)b * T;         // blank stream
    const size_t rstride = (size_t)B * V;

    // ---- init alpha at t=0 and first emit buffers ----
    if (useful) {
        float c0 = (p == 0) ? pb[0] : NEG2;
        float c1 = (p == 0 && act1) ? __ldg(pl) : NEG2;
        sh0[p] = make_float2(c0, c1);
    }
    float eb[KSTEP], el[KSTEP];
#pragma unroll
    for (int j = 0; j < KSTEP; ++j) {
        int tt = 1 + j;
        bool ok = (tt < Tlen);
        eb[j] = ok ? __ldg(pb + tt) : 0.0f;                       // scalar: pb+1 not 16B-aligned
        el[j] = ok ? __ldg(pl + (size_t)tt * rstride) : 0.0f;
    }
    __syncthreads();

    const int nblk = (Tlen - 1 + KSTEP - 1) / KSTEP;

    float c0, c1;
    for (int blk = 0; blk < nblk; ++blk) {
        const int t0 = blk * KSTEP;
        float2* shR = (blk & 1) ? sh1 : sh0;
        float2* shW = (blk & 1) ? sh0 : sh1;

        float2 v = inP ? shR[p] : make_float2(NEG2, NEG2);
        c0 = v.x; c1 = v.y;

        // prefetch emits for next block (scalar loads; L1/L2-resident)
        float nb0[KSTEP], nl0[KSTEP];
        {
            int tb = t0 + KSTEP + 1;
#pragma unroll
            for (int j = 0; j < KSTEP; ++j) {
                int tt = tb + j;
                bool ok = (tt < Tlen);
                nb0[j] = ok ? __ldg(pb + tt) : 0.0f;
                nl0[j] = ok ? __ldg(pl + (size_t)tt * rstride) : 0.0f;
            }
        }

#pragma unroll
        for (int j = 0; j < KSTEP; ++j) {
            int t = t0 + 1 + j;
            float c1l = __shfl_up_sync(0xffffffffu, c1, 1);
            // s0' = logadd2(c0, c1l) + eb   (exp2(0)=1 for the max term)
            float m0 = fmaxf(c0, c1l);
            float d0 = fminf(c0, c1l) - m0;
            float s0 = m0 + lg2(1.0f + ex2(d0)) + eb[j];
            // s1' = logadd3(c1, c0, allow? c1l) + el
            float q  = allow ? c1l : NEG2;
            float h  = fmaxf(c1, c0);
            float lo = fminf(c1, c0);
            float m1 = fmaxf(h, q);
            float l2 = fminf(h, q);
            float r1 = 1.0f + ex2(lo - m1) + ex2(l2 - m1);
            float s1 = m1 + lg2(r1) + el[j];
            bool upd = (t < Tlen);
            c0 = (upd && act0) ? s0 : c0;
            c1 = (upd && act1) ? s1 : c1;
        }

        if (useful) shW[p] = make_float2(c0, c1);
        __syncthreads();

#pragma unroll
        for (int j = 0; j < KSTEP; ++j) { eb[j] = nb0[j]; el[j] = nl0[j]; }
    }

    if (tid == 0) {
        float2* fin = (nblk & 1) ? sh1 : sh0;
        int e = Lb; if (e > P - 1) e = P - 1;
        float a0 = fin[e].x;                              // state 2*Lb
        float a1 = (e >= 1) ? fin[e - 1].y : NEG2;        // state 2*Lb-1
        float mm = fmaxf(a0, a1);
        float l2sum = mm + lg2(ex2(a0 - mm) + ex2(a1 - mm));
        g_costs[b] = -l2sum * 0.69314718055994530942f;    // log2 -> nats
    }
}

// ---------------------------------------------------------------------------
// Kernel 3: deterministic sum of per-example costs.
// ---------------------------------------------------------------------------
__global__ void reduce_k(float* out, int B) {
    float sum = 0.0f;
    for (int i = threadIdx.x; i < B; i += 32) sum += g_costs[i];
#pragma unroll
    for (int o = 16; o; o >>= 1) sum += __shfl_xor_sync(0xffffffffu, sum, o);
    if (threadIdx.x == 0) *out = sum;
}

// ---------------------------------------------------------------------------
extern "C" void kernel_launch(void* const* d_in, const int* in_sizes, int n_in,
                              void* d_out, int out_size)
{
    const float* acts      = (const float*)d_in[0];
    const int*   labels    = (const int*)d_in[1];
    const int*   act_lens  = (const int*)d_in[2];
    const int*   label_len = (const int*)d_in[3];

    int B = in_sizes[2];
    int L = in_sizes[1] / B;
    int V = CTC_V;
    int T = in_sizes[0] / (B * V);

    int rows = T * B;
    softmax_k<<<(rows + 7) / 8, 256>>>(acts, rows, T, B);

    int P  = L + 1;
    int NW = (P + UW - 1) / UW;          // 10 warps for L=256
    int BD = NW * 32;                    // 320
    size_t smem = (size_t)2 * (P + 1) * sizeof(float2);
    ctc_alpha_k<<<B, BD, smem>>>(labels, act_lens, label_len, T, B, L);

    reduce_k<<<1, 32>>>((float*)d_out, B);
}